// round 1
// baseline (speedup 1.0000x reference)
#include <cuda_runtime.h>
#include <math.h>

// Problem constants
#define N_      4
#define C_      21
#define H_      512
#define W_      512
#define PH      171          // pooled spatial size: floor((512+2-3)/3)+1
#define PP      (PH*PH)      // 29241 pooled cells
#define NH      169          // PH - (radius-1)
#define M_      (NH*NH)      // 28561 samples per (n,c)
#define NC      (N_*C_)      // 84
#define ALPHA   5e-4
#define CLIPMIN 1e-6f

// ------------------------- device scratch (static, allocation-free) --------
__device__ float  g_la[NC*PP];          // pooled one-hot labels (0/1)
__device__ float  g_pr[NC*PP];          // pooled probs (max sigmoid + 1e-6)
__device__ double g_gram[NC*3*81];      // per (n,c): v0 la·la (45 tri + 9 sums),
                                        //            v1 pr·pr (45 tri + 9 sums),
                                        //            v2 la·pr (81 full)
__device__ double g_bce;
__device__ double g_valid;
__device__ int    g_lab64;

// ------------------------- kernel 0: init + label dtype sniff --------------
__global__ void k_init(const void* lab) {
    // int64 labels (values < 21) have zero high words at odd int32 positions.
    const int* p = (const int*)lab;
    bool is64 = true;
    #pragma unroll 1
    for (int k = 0; k < 64; k++) {
        if (p[2*k + 1] != 0) { is64 = false; break; }
    }
    g_lab64 = is64 ? 1 : 0;
    g_bce   = 0.0;
    g_valid = 0.0;
}

// ------------------------- kernel 1: fused max-pool + BCE ------------------
// One thread per pooled cell per batch. Windows (k=3,s=3,pad=1) partition the
// 512x512 image, so per-pixel BCE is accumulated exactly once here.
__global__ void __launch_bounds__(128)
k_pool_bce(const float* __restrict__ logits, const void* __restrict__ labv) {
    const int p = blockIdx.x * blockDim.x + threadIdx.x;
    const int n = blockIdx.y;

    float bce_acc = 0.f;
    int   valid   = 0;

    if (p < PP) {
        const int i  = p / PH, j = p - i * PH;
        const int y0 = 3*i - 1, x0 = 3*j - 1;

        const bool is64 = (g_lab64 != 0);
        const long long* L64 = (const long long*)labv;
        const int*       L32 = (const int*)labv;

        int offs[9];
        int labs[9];
        int cnt = 0;
        #pragma unroll
        for (int dy = 0; dy < 3; dy++) {
            #pragma unroll
            for (int dx = 0; dx < 3; dx++) {
                const int y = y0 + dy, x = x0 + dx;
                if (y >= 0 && y < H_ && x >= 0 && x < W_) {
                    const int idx = (n*H_ + y)*W_ + x;
                    const int lv  = is64 ? (int)L64[idx] : L32[idx];
                    offs[cnt] = y*W_ + x;
                    labs[cnt] = lv;
                    cnt++;
                }
            }
        }
        #pragma unroll 9
        for (int k = 0; k < 9; k++)
            if (k < cnt && labs[k] >= 0 && labs[k] < C_) valid++;

        const int ncbase = n * C_;
        #pragma unroll 1
        for (int c = 0; c < C_; c++) {
            const float* __restrict__ base = logits + (size_t)(ncbase + c) * (H_*W_);
            float maxp = 0.f;     // max over (mask ? sigmoid : 0)
            int   anyl = 0;
            #pragma unroll 9
            for (int k = 0; k < 9; k++) {
                if (k >= cnt) break;
                const int   lv = labs[k];
                const bool  m  = (lv >= 0 && lv < C_);
                const float xv = base[offs[k]];
                const float t  = __expf(-fabsf(xv));
                const float u  = __fdividef(1.f, 1.f + t);
                const float sg = (xv >= 0.f) ? u : t * u;
                // stable: bce = softplus(x) - y*x
                const float sp = fmaxf(xv, 0.f) + __logf(1.f + t);
                const float yv = (m && lv == c) ? 1.f : 0.f;
                if (m) bce_acc += sp - yv * xv;
                maxp = fmaxf(maxp, m ? sg : 0.f);
                anyl |= (m && lv == c);
            }
            g_pr[(ncbase + c)*PP + p] = maxp + CLIPMIN;
            g_la[(ncbase + c)*PP + p] = anyl ? 1.f : 0.f;
        }
    }

    // block reduce (double) -> atomic
    double b = (double)bce_acc;
    double v = (double)valid;
    #pragma unroll
    for (int o = 16; o > 0; o >>= 1) {
        b += __shfl_down_sync(0xffffffffu, b, o);
        v += __shfl_down_sync(0xffffffffu, v, o);
    }
    __shared__ double sb[4], sv[4];
    const int lane = threadIdx.x & 31, wid = threadIdx.x >> 5;
    if (lane == 0) { sb[wid] = b; sv[wid] = v; }
    __syncthreads();
    if (threadIdx.x == 0) {
        atomicAdd(&g_bce,   sb[0] + sb[1] + sb[2] + sb[3]);
        atomicAdd(&g_valid, sv[0] + sv[1] + sv[2] + sv[3]);
    }
}

// ------------------------- kernel 2: 9x9 Gram matrices ---------------------
// V=0: la Gram (triangle) + sums; V=1: pr Gram + sums; V=2: la x pr (full).
template<int V>
__global__ void __launch_bounds__(256)
k_gram() {
    const int nc = blockIdx.x;
    const float* __restrict__ A = ((V == 1) ? g_pr : g_la) + (size_t)nc * PP;
    const float* __restrict__ B = g_pr + (size_t)nc * PP;

    constexpr int NACC = (V == 2) ? 81 : 54;
    float acc[NACC];
    #pragma unroll
    for (int k = 0; k < NACC; k++) acc[k] = 0.f;

    for (int m = threadIdx.x; m < M_; m += 256) {
        const int i = m / NH, j = m - i * NH;
        const float* pa = A + i*PH + j;
        float a[9];
        #pragma unroll
        for (int d = 0; d < 9; d++) a[d] = pa[(d/3)*PH + (d%3)];
        if (V == 2) {
            const float* pb = B + i*PH + j;
            float bb[9];
            #pragma unroll
            for (int d = 0; d < 9; d++) bb[d] = pb[(d/3)*PH + (d%3)];
            #pragma unroll
            for (int d = 0; d < 9; d++)
                #pragma unroll
                for (int e = 0; e < 9; e++)
                    acc[d*9 + e] += a[d] * bb[e];
        } else {
            int k = 0;
            #pragma unroll
            for (int d = 0; d < 9; d++)
                #pragma unroll
                for (int e = d; e < 9; e++)
                    acc[k++] += a[d] * a[e];
            #pragma unroll
            for (int d = 0; d < 9; d++) acc[45 + d] += a[d];
        }
    }

    // warp reduce each accumulator in double, stage per-warp, final sum
    __shared__ double smem[8][81];
    const int lane = threadIdx.x & 31, wid = threadIdx.x >> 5;
    #pragma unroll 1
    for (int k = 0; k < NACC; k++) {
        double x = (double)acc[k];
        #pragma unroll
        for (int o = 16; o > 0; o >>= 1) x += __shfl_down_sync(0xffffffffu, x, o);
        if (lane == 0) smem[wid][k] = x;
    }
    __syncthreads();
    double* out = g_gram + (size_t)(nc*3 + V) * 81;
    for (int k = threadIdx.x; k < NACC; k += 256) {
        double s = 0.0;
        #pragma unroll
        for (int w = 0; w < 8; w++) s += smem[w][k];
        out[k] = s;
    }
}

// ------------------------- kernel 3: per-(n,c) linear algebra + combine ----
__global__ void __launch_bounds__(128)
k_finalize(float* __restrict__ outp) {
    __shared__ double ssum[128];
    const int t = threadIdx.x;
    double rmi = 0.0;

    if (t < NC) {
        const double* G0 = g_gram + (size_t)(t*3 + 0)*81;  // la
        const double* G1 = g_gram + (size_t)(t*3 + 1)*81;  // pr
        const double* G2 = g_gram + (size_t)(t*3 + 2)*81;  // la x pr

        double Sla[9], Spr[9];
        for (int d = 0; d < 9; d++) { Sla[d] = G0[45+d]; Spr[d] = G1[45+d]; }
        const double invM = 1.0 / (double)M_;

        double Cla[9][9], P[9][9], Bm[9][9];
        {
            int k = 0;
            for (int d = 0; d < 9; d++)
                for (int e = d; e < 9; e++) {
                    const double cl = G0[k] - Sla[d]*Sla[e]*invM;
                    const double cp = G1[k] - Spr[d]*Spr[e]*invM;
                    Cla[d][e] = Cla[e][d] = cl;
                    P[d][e]   = P[e][d]   = cp;
                    k++;
                }
            for (int d = 0; d < 9; d++) P[d][d] += ALPHA;
            for (int d = 0; d < 9; d++)
                for (int e = 0; e < 9; e++)
                    Bm[d][e] = G2[d*9 + e] - Sla[d]*Spr[e]*invM;
        }

        // Cholesky of P = L L^T
        double Lm[9][9];
        for (int a = 0; a < 9; a++) {
            for (int b = 0; b <= a; b++) {
                double s = P[a][b];
                for (int c = 0; c < b; c++) s -= Lm[a][c]*Lm[b][c];
                if (a == b) Lm[a][a] = sqrt(fmax(s, 1e-300));
                else        Lm[a][b] = s / Lm[b][b];
            }
        }
        // W = B L^{-T}  (row-wise forward substitution)
        double Wm[9][9];
        for (int d = 0; d < 9; d++)
            for (int e = 0; e < 9; e++) {
                double s = Bm[d][e];
                for (int k = 0; k < e; k++) s -= Wm[d][k]*Lm[e][k];
                Wm[d][e] = s / Lm[e][e];
            }
        // A2 = Cla - W W^T + alpha I
        double A2[9][9];
        for (int d = 0; d < 9; d++)
            for (int g = 0; g < 9; g++) {
                double s = 0.0;
                for (int k = 0; k < 9; k++) s += Wm[d][k]*Wm[g][k];
                A2[d][g] = Cla[d][g] - s;
            }
        for (int d = 0; d < 9; d++) A2[d][d] += ALPHA;
        // Cholesky of A2; rmi = sum log(diag + 1e-8)
        double sum = 0.0;
        for (int a = 0; a < 9; a++) {
            for (int b = 0; b <= a; b++) {
                double s = A2[a][b];
                for (int c = 0; c < b; c++) s -= Lm[a][c]*Lm[b][c];
                if (a == b) {
                    const double dv = sqrt(fmax(s, 1e-300));
                    Lm[a][a] = dv;
                    sum += log(dv + 1e-8);
                } else {
                    Lm[a][b] = s / Lm[b][b];
                }
            }
        }
        rmi = sum;
    }

    ssum[t] = rmi;
    __syncthreads();
    for (int s = 64; s > 0; s >>= 1) {
        if (t < s) ssum[t] += ssum[t + s];
        __syncthreads();
    }
    if (t == 0) {
        const double rmi_total = ssum[0] / (double)(N_ * 9);   // mean over n, /HALF_D, sum over c
        const double bce_loss  = g_bce / (g_valid + 1.0);
        outp[0] = (float)(0.5 * bce_loss + 0.5 * rmi_total);
    }
}

// ------------------------- launch ------------------------------------------
extern "C" void kernel_launch(void* const* d_in, const int* in_sizes, int n_in,
                              void* d_out, int out_size) {
    const float* logits = (const float*)d_in[0];
    const void*  labels = d_in[1];

    k_init<<<1, 1>>>(labels);
    dim3 g1((PP + 127) / 128, N_);
    k_pool_bce<<<g1, 128>>>(logits, labels);
    k_gram<0><<<NC, 256>>>();
    k_gram<1><<<NC, 256>>>();
    k_gram<2><<<NC, 256>>>();
    k_finalize<<<1, 128>>>((float*)d_out);
}